// round 11
// baseline (speedup 1.0000x reference)
#include <cuda_runtime.h>
#include <math.h>
#include <stdint.h>

#define L_  4
#define B_  8
#define H_  16
#define S_  4096
#define HD_ 64
#define D_  1024
#define Q_  4
#define V_  32000
#define SP_ (S_ + Q_)      // 4100
#define M32 (B_ * Q_)      // 32
#define SCALE_ 0.125f      // 1/sqrt(64)
#define BK_ 128            // k per tile
#define HALF_ 2048         // rows per attention split block

// partial-buffer offsets (floats) inside g_part
#define PQ_OFF  0                         // qkv partials  4*32*3072
#define PO_OFF  393216                    // out_w partials 8*32*1024
#define PF1_OFF 655360                    // fc1 partials  4*32*4096
#define PF2_OFF 1179648                   // fc2 partials  8*32*1024

// attn smem layout (floats): ring [3][64 rows][16 f4] first (16B aligned)
#define QS_OFF   12288
#define KN_OFF   12544
#define VN_OFF   12800
#define RED_OFF  13056
#define MLS_OFF  13312
#define OPA_OFF  13344
#define SCT_OFF  15392                    // [2052][4]
#define ATTN_SM_F (SCT_OFF + 2052 * 4)    // 23600 floats = 94400 B

// ------------------------- scratch (no allocs allowed) ----------------------
__device__ float g_x[M32 * D_];
__device__ float g_part[2097152];             // split-K partials (8 MB)
__device__ float g_opart[2 * 128 * 4 * 64];   // attn partial O [bh*2+j][qq][d]
__device__ float g_ms[128 * 2 * 8];           // attn [bh*2+j][m0..3, s0..3]

// ------------------------------ helpers -------------------------------------
__device__ __forceinline__ void fma2(unsigned long long& d,
                                     unsigned long long a, unsigned long long b) {
    asm("fma.rn.f32x2 %0, %1, %2, %0;" : "+l"(d) : "l"(a), "l"(b));
}
__device__ __forceinline__ void cp_async16(uint32_t dst, const void* src) {
    asm volatile("cp.async.cg.shared.global [%0], [%1], 16;" :: "r"(dst), "l"(src));
}
__device__ __forceinline__ void cp_commit() {
    asm volatile("cp.async.commit_group;");
}
template <int N>
__device__ __forceinline__ void cp_wait() {
    asm volatile("cp.async.wait_group %0;" :: "n"(N));
}
__device__ __forceinline__ void cp_chunk(uint32_t slot_addr, const float4* src, int t) {
#pragma unroll
    for (int i = 0; i < 4; i++)
        cp_async16(slot_addr + (uint32_t)(t + i * 256) * 16, src + t + i * 256);
    cp_commit();
}

// aload=1: inline attn-combine A staging (out_w GEMM)
__device__ __forceinline__ float4 ld_a_combine(int mrow, int col) {
    int b = mrow >> 2, qq = mrow & 3;
    int h = col >> 6, d = col & 63;
    int bh = b * 16 + h;
    float m0 = g_ms[(bh * 2 + 0) * 8 + qq], s0 = g_ms[(bh * 2 + 0) * 8 + 4 + qq];
    float m1 = g_ms[(bh * 2 + 1) * 8 + qq], s1 = g_ms[(bh * 2 + 1) * 8 + 4 + qq];
    float M = fmaxf(m0, m1);
    float w0 = __expf(m0 - M), w1 = __expf(m1 - M);
    float inv = 1.f / (s0 * w0 + s1 * w1);
    w0 *= inv; w1 *= inv;
    float4 o0 = *reinterpret_cast<const float4*>(&g_opart[((size_t)(bh * 2 + 0) * 4 + qq) * 64 + d]);
    float4 o1 = *reinterpret_cast<const float4*>(&g_opart[((size_t)(bh * 2 + 1) * 4 + qq) * 64 + d]);
    return make_float4(o0.x * w0 + o1.x * w1, o0.y * w0 + o1.y * w1,
                       o0.z * w0 + o1.z * w1, o0.w * w0 + o1.w * w1);
}

// aload=2: A = relu(sum of 4 k-split slices) (fc2 GEMM; slice stride 32*K)
__device__ __forceinline__ float4 ld_a_relu4(const float* p, int K) {
    float4 r = *reinterpret_cast<const float4*>(p);
#pragma unroll
    for (int s = 1; s < 4; s++) {
        float4 u = *reinterpret_cast<const float4*>(p + (size_t)s * 32 * K);
        r.x += u.x; r.y += u.y; r.z += u.z; r.w += u.w;
    }
    r.x = fmaxf(r.x, 0.f); r.y = fmaxf(r.y, 0.f);
    r.z = fmaxf(r.z, 0.f); r.w = fmaxf(r.w, 0.f);
    return r;
}

// aload=3: A = x + sum of 8 out_w partial slices (fc1 GEMM; K=1024)
__device__ __forceinline__ float4 ld_a_xsum(const float* p, size_t off) {
    float4 r = *reinterpret_cast<const float4*>(&g_x[off]);
#pragma unroll
    for (int s = 0; s < 8; s++) {
        float4 u = *reinterpret_cast<const float4*>(p + off + (size_t)s * 32 * D_);
        r.x += u.x; r.y += u.y; r.z += u.z; r.w += u.w;
    }
    return r;
}

// ------------------------------ embedding -----------------------------------
__global__ void embed_kernel(const int* __restrict__ ids, const int* __restrict__ pos,
                             const float* __restrict__ emb, const float* __restrict__ pemb) {
    int m = blockIdx.x;
    int id = ids[m];
    int p  = pos[m];
    const float* e  = emb  + (size_t)id * D_;
    const float* pe = pemb + (size_t)p  * D_;
    for (int d = threadIdx.x; d < D_; d += blockDim.x)
        g_x[m * D_ + d] = e[d] + pe[d];
}

// ------------------------------ skinny GEMM ---------------------------------
__global__ void __launch_bounds__(256, 3)
gemm32_kernel(const float* __restrict__ A, const float* __restrict__ W,
              const float* __restrict__ res, float* __restrict__ Cout,
              int N, int K, int kslen, int mode, int aload) {
    __shared__ float4 w_sm[32 * 32];   // [row][col4]
    __shared__ float4 a_sm[32 * 32];   // [col4][row^col4] swizzled

    int t = threadIdx.x;
    int m = t & 31;
    int g = t >> 5;
    int nblocks = N >> 5;
    int nb = blockIdx.x % nblocks;
    int ks = blockIdx.x / nblocks;
    int k0 = ks * kslen;

    int lrow = t >> 5;
    int lcol = t & 31;
    const float* Wg = W + (size_t)(nb * 32 + lrow) * K + k0 + (size_t)lcol * 4;
    const float* Ag = A + (size_t)lrow * K + k0 + (size_t)lcol * 4;

    int nt = kslen >> 7;

    float4 wreg[4], areg[4];
#pragma unroll
    for (int i = 0; i < 4; i++) {
        wreg[i] = *reinterpret_cast<const float4*>(Wg + (size_t)(8 * i) * K);
        areg[i] = (aload == 0)
                ? *reinterpret_cast<const float4*>(Ag + (size_t)(8 * i) * K)
                : (aload == 1)
                ? ld_a_combine(lrow + 8 * i, k0 + lcol * 4)
                : (aload == 2)
                ? ld_a_relu4(Ag + (size_t)(8 * i) * K, K)
                : ld_a_xsum(A, (size_t)(lrow + 8 * i) * K + k0 + lcol * 4);
    }

    unsigned long long acc[4][2];
#pragma unroll
    for (int j = 0; j < 4; j++) { acc[j][0] = 0ull; acc[j][1] = 0ull; }

    for (int it = 0; it < nt; it++) {
#pragma unroll
        for (int i = 0; i < 4; i++) {
            int row = lrow + 8 * i;
            w_sm[row * 32 + lcol] = wreg[i];
            a_sm[lcol * 32 + (row ^ lcol)] = areg[i];
        }
        __syncthreads();

        if (it + 1 < nt) {
            int kc = (it + 1) * BK_;
#pragma unroll
            for (int i = 0; i < 4; i++) {
                wreg[i] = *reinterpret_cast<const float4*>(Wg + (size_t)(8 * i) * K + kc);
                areg[i] = (aload == 0)
                        ? *reinterpret_cast<const float4*>(Ag + (size_t)(8 * i) * K + kc)
                        : (aload == 1)
                        ? ld_a_combine(lrow + 8 * i, k0 + kc + lcol * 4)
                        : (aload == 2)
                        ? ld_a_relu4(Ag + (size_t)(8 * i) * K + kc, K)
                        : ld_a_xsum(A, (size_t)(lrow + 8 * i) * K + k0 + kc + lcol * 4);
            }
        }

        const float4* wrow = w_sm + g * 4 * 32;
#pragma unroll 8
        for (int k4 = 0; k4 < 32; k4++) {
            ulonglong2 av = *reinterpret_cast<const ulonglong2*>(&a_sm[k4 * 32 + (m ^ k4)]);
            ulonglong2 w0 = *reinterpret_cast<const ulonglong2*>(&wrow[k4]);
            ulonglong2 w1 = *reinterpret_cast<const ulonglong2*>(&wrow[32 + k4]);
            ulonglong2 w2 = *reinterpret_cast<const ulonglong2*>(&wrow[64 + k4]);
            ulonglong2 w3 = *reinterpret_cast<const ulonglong2*>(&wrow[96 + k4]);
            fma2(acc[0][0], av.x, w0.x); fma2(acc[0][1], av.y, w0.y);
            fma2(acc[1][0], av.x, w1.x); fma2(acc[1][1], av.y, w1.y);
            fma2(acc[2][0], av.x, w2.x); fma2(acc[2][1], av.y, w2.y);
            fma2(acc[3][0], av.x, w3.x); fma2(acc[3][1], av.y, w3.y);
        }
        __syncthreads();
    }

    int n0 = nb * 32 + g * 4;
    if (kslen == K) {
#pragma unroll
        for (int j = 0; j < 4; j++) {
            float2 lo = *reinterpret_cast<float2*>(&acc[j][0]);
            float2 hi = *reinterpret_cast<float2*>(&acc[j][1]);
            float v = (lo.x + lo.y) + (hi.x + hi.y);
            int n = n0 + j;
            if (mode == 1)      v += res[(size_t)m * N + n];
            else if (mode == 2) v = fmaxf(v, 0.f);
            Cout[(size_t)m * N + n] = v;
        }
    } else {
#pragma unroll
        for (int j = 0; j < 4; j++) {
            float2 lo = *reinterpret_cast<float2*>(&acc[j][0]);
            float2 hi = *reinterpret_cast<float2*>(&acc[j][1]);
            Cout[(size_t)(ks * 32 + m) * N + n0 + j] = (lo.x + lo.y) + (hi.x + hi.y);
        }
    }
}

// combined per-layer reduce: x += sum8(PO) + sum8(PF2)
__global__ void reduce2_kernel(const float* __restrict__ PO8,
                               const float* __restrict__ PF28) {
    int i = blockIdx.x * 256 + threadIdx.x;   // 32*1024 elements
    float s = g_x[i];
#pragma unroll
    for (int ks = 0; ks < 8; ks++) {
        s += PO8[(size_t)ks * 32 * D_ + i];
        s += PF28[(size_t)ks * 32 * D_ + i];
    }
    g_x[i] = s;
}

// ------------- split attention: cp.async ring-buffered K/V streams ----------
__global__ void __launch_bounds__(256, 2)
attn_split_kernel(const float* __restrict__ partQ,
                  const float* __restrict__ pk, const float* __restrict__ pv,
                  float* __restrict__ ok, float* __restrict__ ov) {
    extern __shared__ float sm[];
    float4* ring = reinterpret_cast<float4*>(sm);   // [3][1024] float4
    float* q_sm  = sm + QS_OFF;    // [4][64] pre-scaled
    float* kn    = sm + KN_OFF;    // new K rows [4][64]
    float* vn    = sm + VN_OFF;    // new V rows [4][64]
    float* red   = sm + RED_OFF;   // [256]
    float* mls   = sm + MLS_OFF;   // [4] local max (pad 32)
    float* opart = sm + OPA_OFF;   // [8 warps][4 qq][64 d]
    float* scT   = sm + SCT_OFF;   // [2052][4] interleaved scores

    uint32_t ring_u32;
    {
        uint64_t tmp;
        asm("cvta.to.shared.u64 %0, %1;" : "=l"(tmp) : "l"(ring));
        ring_u32 = (uint32_t)tmp;
    }

    int t = threadIdx.x;
    int bh = blockIdx.x >> 1;
    int j  = blockIdx.x & 1;
    int b = bh >> 4;
    int h = bh & 15;
    int s0 = j * HALF_;
    int nrows = HALF_ + (j ? Q_ : 0);

    const float4* kb4  = reinterpret_cast<const float4*>(pk + (size_t)bh * S_ * HD_);
    const float4* vb4  = reinterpret_cast<const float4*>(pv + (size_t)bh * S_ * HD_);
    float4*       okb4 = reinterpret_cast<float4*>(ok + (size_t)bh * SP_ * HD_);
    float4*       ovb4 = reinterpret_cast<float4*>(ov + (size_t)bh * SP_ * HD_);

    // prologue: K chunks 0,1 into slots 0,1
    cp_chunk(ring_u32,         kb4 + (size_t)s0 * 16,        t);
    cp_chunk(ring_u32 + 16384, kb4 + (size_t)(s0 + 64) * 16, t);

    {   // fused qkv split-K reduce: sum 4 partial slices (N=3072)
        int qq = t >> 6, d = t & 63;
        int m = b * Q_ + qq;
        int col = h * HD_ + d;
        float qv = 0.f, kv = 0.f, vv = 0.f;
#pragma unroll
        for (int s = 0; s < 4; s++) {
            const float* pr = partQ + (size_t)(s * 32 + m) * (3 * D_) + col;
            qv += pr[0];
            kv += pr[D_];
            vv += pr[2 * D_];
        }
        q_sm[t] = qv * SCALE_;
        kn[t]   = kv;
        vn[t]   = vv;
    }
    __syncthreads();

    int w   = t >> 5;   // 0..7
    int l   = t & 31;
    int sub = l >> 4;
    int dq  = l & 15;

    float4 q0 = *reinterpret_cast<const float4*>(q_sm +       dq * 4);
    float4 q1 = *reinterpret_cast<const float4*>(q_sm +  64 + dq * 4);
    float4 q2 = *reinterpret_cast<const float4*>(q_sm + 128 + dq * 4);
    float4 q3 = *reinterpret_cast<const float4*>(q_sm + 192 + dq * 4);

    // ---- pass 1: K chunks -> scores + pres_k ----
    for (int c = 0; c < 32; c++) {
        if (c < 31) cp_wait<1>(); else cp_wait<0>();
        __syncthreads();
        if (c + 2 < 32)
            cp_chunk(ring_u32 + (uint32_t)((c + 2) % 3) * 16384,
                     kb4 + (size_t)(s0 + (c + 2) * 64) * 16, t);

        const float4* ch = ring + (c % 3) * 1024;
        float4* dst = okb4 + (size_t)(s0 + c * 64) * 16;
#pragma unroll
        for (int i = 0; i < 4; i++)
            dst[t + i * 256] = ch[t + i * 256];

#pragma unroll
        for (int u = 0; u < 4; u++) {
            int ric = w * 8 + u * 2 + sub;
            float4 k = ch[ric * 16 + dq];
            float p0 = k.x * q0.x + k.y * q0.y + k.z * q0.z + k.w * q0.w;
            float p1 = k.x * q1.x + k.y * q1.y + k.z * q1.z + k.w * q1.w;
            float p2 = k.x * q2.x + k.y * q2.y + k.z * q2.z + k.w * q2.w;
            float p3 = k.x * q3.x + k.y * q3.y + k.z * q3.z + k.w * q3.w;
#pragma unroll
            for (int off = 1; off <= 8; off <<= 1) {
                p0 += __shfl_xor_sync(0xffffffffu, p0, off);
                p1 += __shfl_xor_sync(0xffffffffu, p1, off);
                p2 += __shfl_xor_sync(0xffffffffu, p2, off);
                p3 += __shfl_xor_sync(0xffffffffu, p3, off);
            }
            if (dq == 0)
                *reinterpret_cast<float4*>(scT + (c * 64 + ric) * 4) = make_float4(p0, p1, p2, p3);
        }
    }
    if (j == 1 && w < 2) {   // new K rows 4096..4099 (local 2048..2051)
        int r2 = w * 2 + sub;
        int rowl = HALF_ + r2;
        float4 kv = *reinterpret_cast<const float4*>(kn + r2 * HD_ + dq * 4);
        okb4[(size_t)(S_ + r2) * 16 + dq] = kv;
        float p0 = kv.x * q0.x + kv.y * q0.y + kv.z * q0.z + kv.w * q0.w;
        float p1 = kv.x * q1.x + kv.y * q1.y + kv.z * q1.z + kv.w * q1.w;
        float p2 = kv.x * q2.x + kv.y * q2.y + kv.z * q2.z + kv.w * q2.w;
        float p3 = kv.x * q3.x + kv.y * q3.y + kv.z * q3.z + kv.w * q3.w;
#pragma unroll
        for (int off = 1; off <= 8; off <<= 1) {
            p0 += __shfl_xor_sync(0xffffffffu, p0, off);
            p1 += __shfl_xor_sync(0xffffffffu, p1, off);
            p2 += __shfl_xor_sync(0xffffffffu, p2, off);
            p3 += __shfl_xor_sync(0xffffffffu, p3, off);
        }
        if (dq == 0)
            *reinterpret_cast<float4*>(scT + rowl * 4) = make_float4(p0, p1, p2, p3);
    }
    __syncthreads();

    // issue V chunks 0,1 now — they load while softmax runs
    cp_chunk(ring_u32,         vb4 + (size_t)s0 * 16,        t);
    cp_chunk(ring_u32 + 16384, vb4 + (size_t)(s0 + 64) * 16, t);

    // ---- local softmax stats ----
    {
        int qq = t & 3, sidx = t >> 2;
        float mx = -1e30f;
        for (int s = sidx; s < nrows; s += 64) mx = fmaxf(mx, scT[s * 4 + qq]);
        red[t] = mx;
        __syncthreads();
        for (int wd = 128; wd >= 4; wd >>= 1) {
            if (t < wd) red[t] = fmaxf(red[t], red[t + wd]);
            __syncthreads();
        }
        if (t < 4) mls[t] = red[t];
        __syncthreads();
        float gm = mls[qq];
        float sum = 0.f;
        for (int s = sidx; s < nrows; s += 64) {
            float e = __expf(scT[s * 4 + qq] - gm);
            scT[s * 4 + qq] = e;
            sum += e;
        }
        __syncthreads();
        red[t] = sum;
        __syncthreads();
        for (int wd = 128; wd >= 4; wd >>= 1) {
            if (t < wd) red[t] += red[t + wd];
            __syncthreads();
        }
        if (t < 4) {
            int bj = bh * 2 + j;
            g_ms[bj * 8 + t]     = mls[t];
            g_ms[bj * 8 + 4 + t] = red[t];
        }
        __syncthreads();
    }

    // ---- pass 2: V chunks -> unnormalized partial O + pres_v ----
    float4 a0 = make_float4(0.f, 0.f, 0.f, 0.f);
    float4 a1 = a0, a2 = a0, a3 = a0;

    for (int c = 0; c < 32; c++) {
        if (c < 31) cp_wait<1>(); else cp_wait<0>();
        __syncthreads();
        if (c + 2 < 32)
            cp_chunk(ring_u32 + (uint32_t)((c + 2) % 3) * 16384,
                     vb4 + (size_t)(s0 + (c + 2) * 64) * 16, t);

        const float4* ch = ring + (c % 3) * 1024;
        float4* dst = ovb4 + (size_t)(s0 + c * 64) * 16;
#pragma unroll
        for (int i = 0; i < 4; i++)
            dst[t + i * 256] = ch[t + i * 256];

#pragma unroll
        for (int u = 0; u < 4; u++) {
            int ric = w * 8 + u * 2 + sub;
            float4 v = ch[ric * 16 + dq];
            float4 p = *reinterpret_cast<const float4*>(scT + (c * 64 + ric) * 4);
            a0.x += p.x * v.x; a0.y += p.x * v.y; a0.z += p.x * v.z; a0.w += p.x * v.w;
            a1.x += p.y * v.x; a1.y += p.y * v.y; a1.z += p.y * v.z; a1.w += p.y * v.w;
            a2.x += p.z * v.x; a2.y += p.z * v.y; a2.z += p.z * v.z; a2.w += p.z * v.w;
            a3.x += p.w * v.x; a3.y += p.w * v.y; a3.z += p.w * v.z; a3.w += p.w * v.w;
        }
    }
    if (j == 1 && w < 2) {
        int r2 = w * 2 + sub;
        int rowl = HALF_ + r2;
        float4 vv = *reinterpret_cast<const float4*>(vn + r2 * HD_ + dq * 4);
        ovb4[(size_t)(S_ + r2) * 16 + dq] = vv;
        float4 p = *reinterpret_cast<const float4*>(scT + rowl * 4);
        a0.x += p.x * vv.x; a0.y += p.x * vv.y; a0.z += p.x * vv.z; a0.w += p.x * vv.w;
        a1.x += p.y * vv.x; a1.y += p.y * vv.y; a1.z += p.y * vv.z; a1.w += p.y * vv.w;
        a2.x += p.z * vv.x; a2.y += p.z * vv.y; a2.z += p.z * vv.z; a2.w += p.z * vv.w;
        a3.x += p.w * vv.x; a3.y += p.w * vv.y; a3.z += p.w * vv.z; a3.w += p.w * vv.w;
    }

    a0.x += __shfl_xor_sync(0xffffffffu, a0.x, 16); a0.y += __shfl_xor_sync(0xffffffffu, a0.y, 16);
    a0.z += __shfl_xor_sync(0xffffffffu, a0.z, 16); a0.w += __shfl_xor_sync(0xffffffffu, a0.w, 16);
    a1.x += __shfl_xor_sync(0xffffffffu, a1.x, 16); a1.y += __shfl_xor_sync(0xffffffffu, a1.y, 16);
    a1.z += __shfl_xor_sync(0xffffffffu, a1.z, 16); a1.w += __shfl_xor_sync(0xffffffffu, a1.w, 16);
    a2.x += __shfl_xor_sync(0xffffffffu, a2.x, 16); a2.y += __shfl_xor_sync(0xffffffffu, a2.y, 16);
    a2.z += __shfl_xor_sync(0xffffffffu, a2.z, 16); a2.w += __shfl_xor_sync(0xffffffffu, a2.w, 16);
    a3.x += __shfl_xor_sync(0xffffffffu, a3.x, 16); a3.y += __shfl_xor_sync(0xffffffffu, a3.y, 16);
    a3.z += __shfl_xor_sync(0xffffffffu, a3.z, 16); a3.w += __shfl_xor_sync(0xffffffffu, a3.w, 16);

    if (sub == 0) {
        *reinterpret_cast<float4*>(opart + (w * 4 + 0) * 64 + dq * 4) = a0;
        *reinterpret_cast<float4*>(opart + (w * 4 + 1) * 64 + dq * 4) = a1;
        *reinterpret_cast<float4*>(opart + (w * 4 + 2) * 64 + dq * 4) = a2;
        *reinterpret_cast<float4*>(opart + (w * 4 + 3) * 64 + dq * 4) = a3;
    }
    __syncthreads();

    {   // cross-warp reduce, write UNNORMALIZED partial to scratch
        int qq = t >> 6, d = t & 63;
        float s = 0.f;
#pragma unroll
        for (int ww = 0; ww < 8; ww++)
            s += opart[(ww * 4 + qq) * 64 + d];
        g_opart[((size_t)(bh * 2 + j) * 4 + qq) * 64 + d] = s;
    }
}

// ------------------------------- launcher -----------------------------------
extern "C" void kernel_launch(void* const* d_in, const int* in_sizes, int n_in,
                              void* d_out, int out_size) {
    const int*   ids    = (const int*)d_in[0];
    const int*   pos    = (const int*)d_in[1];
    const float* past_k = (const float*)d_in[2];
    const float* past_v = (const float*)d_in[3];
    const float* emb    = (const float*)d_in[4];
    const float* pemb   = (const float*)d_in[5];
    const float* qkv_w  = (const float*)d_in[6];
    const float* out_w  = (const float*)d_in[7];
    const float* fc1_w  = (const float*)d_in[8];
    const float* fc2_w  = (const float*)d_in[9];
    const float* lm_w   = (const float*)d_in[10];

    float* out    = (float*)d_out;
    float* logits = out;
    float* pres_k = out + (size_t)M32 * V_;
    float* pres_v = pres_k + (size_t)L_ * B_ * H_ * SP_ * HD_;

    float *x, *part;
    cudaGetSymbolAddress((void**)&x,    g_x);
    cudaGetSymbolAddress((void**)&part, g_part);

    const int ATTN_SMEM = ATTN_SM_F * 4;   // 94400 B
    cudaFuncSetAttribute(attn_split_kernel, cudaFuncAttributeMaxDynamicSharedMemorySize, ATTN_SMEM);

    embed_kernel<<<M32, 256>>>(ids, pos, emb, pemb);

    for (int l = 0; l < L_; l++) {
        // qkv = x @ qkv_w^T       N=3072 K=1024, splitK4 -> 384 blocks (partials)
        gemm32_kernel<<<96 * 4, 256>>>(x, qkv_w + (size_t)l * 3 * D_ * D_,
                                       nullptr, part + PQ_OFF, 3 * D_, D_, D_ / 4, 0, 0);

        // attention (fused qkv reduce; writes partial O + stats)
        attn_split_kernel<<<B_ * H_ * 2, 256, ATTN_SMEM>>>(
            part + PQ_OFF,
            past_k + (size_t)l * B_ * H_ * S_ * HD_,
            past_v + (size_t)l * B_ * H_ * S_ * HD_,
            pres_k + (size_t)l * B_ * H_ * SP_ * HD_,
            pres_v + (size_t)l * B_ * H_ * SP_ * HD_);

        // o @ out_w^T partials    N=1024 K=1024, splitK8; A = inline combine
        gemm32_kernel<<<32 * 8, 256>>>(nullptr, out_w + (size_t)l * D_ * D_,
                                       nullptr, part + PO_OFF, D_, D_, D_ / 8, 0, 1);

        // fc1 partials            N=4096 K=1024, splitK4; A = x + sum8(out partials)
        gemm32_kernel<<<128 * 4, 256>>>(part + PO_OFF, fc1_w + (size_t)l * 4 * D_ * D_,
                                        nullptr, part + PF1_OFF, 4 * D_, D_, D_ / 4, 0, 3);

        // fc2 partials            N=1024 K=4096, splitK8; A = relu(sum4 fc1 partials)
        gemm32_kernel<<<32 * 8, 256>>>(part + PF1_OFF, fc2_w + (size_t)l * D_ * 4 * D_,
                                       nullptr, part + PF2_OFF, D_, 4 * D_, 4 * D_ / 8, 0, 2);

        // x += sum8(out partials) + sum8(fc2 partials)
        reduce2_kernel<<<(32 * D_) / 256, 256>>>(part + PO_OFF, part + PF2_OFF);
    }

    // logits = x @ lm_head^T      N=32000 K=1024, 1000 blocks
    gemm32_kernel<<<1000, 256>>>(x, lm_w, nullptr, logits, V_, D_, D_, 0, 0);
}

// round 12
// speedup vs baseline: 1.0736x; 1.0736x over previous
#include <cuda_runtime.h>
#include <math.h>
#include <stdint.h>

#define L_  4
#define B_  8
#define H_  16
#define S_  4096
#define HD_ 64
#define D_  1024
#define Q_  4
#define V_  32000
#define SP_ (S_ + Q_)      // 4100
#define M32 (B_ * Q_)      // 32
#define SCALE_ 0.125f      // 1/sqrt(64)
#define BK_ 128            // k per tile
#define HALF_ 2048         // rows per attention split block

// partial-buffer offsets (floats) inside g_part (r8 layout)
#define PQ_OFF  0                         // qkv partials  4*32*3072
#define PO_OFF  393216                    // out_w partials 8*32*1024
#define PF1_OFF 655360                    // fc1 partials  4*32*4096
#define PF2_OFF 1179648                   // fc2 partials  8*32*1024

#define GEMM_SMEM_B 98304                 // 2*32KB W + 2*16KB A

// ------------------------- scratch (no allocs allowed) ----------------------
__device__ float g_x[M32 * D_];
__device__ float g_h[M32 * 4 * D_];
__device__ float g_part[2097152];             // split-K partials (8 MB)
__device__ float g_opart[2 * 128 * 4 * 64];   // attn partial O [bh*2+j][qq][d]
__device__ float g_ms[128 * 2 * 8];           // attn [bh*2+j][m0..3, s0..3]

// ------------------------------ helpers -------------------------------------
__device__ __forceinline__ void fma2(unsigned long long& d,
                                     unsigned long long a, unsigned long long b) {
    asm("fma.rn.f32x2 %0, %1, %2, %0;" : "+l"(d) : "l"(a), "l"(b));
}
__device__ __forceinline__ void cp_async16(uint32_t dst, const void* src) {
    asm volatile("cp.async.cg.shared.global [%0], [%1], 16;" :: "r"(dst), "l"(src));
}
__device__ __forceinline__ void cp_commit() {
    asm volatile("cp.async.commit_group;");
}
template <int N>
__device__ __forceinline__ void cp_wait() {
    asm volatile("cp.async.wait_group %0;" :: "n"(N));
}
__device__ __forceinline__ uint32_t smem_u32(const void* p) {
    uint64_t tmp;
    asm("cvta.to.shared.u64 %0, %1;" : "=l"(tmp) : "l"(p));
    return (uint32_t)tmp;
}

// aload=1: inline attn-combine A staging (out_w GEMM)
__device__ __forceinline__ float4 ld_a_combine(int mrow, int col) {
    int b = mrow >> 2, qq = mrow & 3;
    int h = col >> 6, d = col & 63;
    int bh = b * 16 + h;
    float m0 = g_ms[(bh * 2 + 0) * 8 + qq], s0 = g_ms[(bh * 2 + 0) * 8 + 4 + qq];
    float m1 = g_ms[(bh * 2 + 1) * 8 + qq], s1 = g_ms[(bh * 2 + 1) * 8 + 4 + qq];
    float M = fmaxf(m0, m1);
    float w0 = __expf(m0 - M), w1 = __expf(m1 - M);
    float inv = 1.f / (s0 * w0 + s1 * w1);
    w0 *= inv; w1 *= inv;
    float4 o0 = *reinterpret_cast<const float4*>(&g_opart[((size_t)(bh * 2 + 0) * 4 + qq) * 64 + d]);
    float4 o1 = *reinterpret_cast<const float4*>(&g_opart[((size_t)(bh * 2 + 1) * 4 + qq) * 64 + d]);
    return make_float4(o0.x * w0 + o1.x * w1, o0.y * w0 + o1.y * w1,
                       o0.z * w0 + o1.z * w1, o0.w * w0 + o1.w * w1);
}

// ------------------------------ embedding -----------------------------------
__global__ void embed_kernel(const int* __restrict__ ids, const int* __restrict__ pos,
                             const float* __restrict__ emb, const float* __restrict__ pemb) {
    int m = blockIdx.x;
    int id = ids[m];
    int p  = pos[m];
    const float* e  = emb  + (size_t)id * D_;
    const float* pe = pemb + (size_t)p  * D_;
    for (int d = threadIdx.x; d < D_; d += blockDim.x)
        g_x[m * D_ + d] = e[d] + pe[d];
}

// ------------------------------ skinny GEMM, N-tile 64 ----------------------
// C[m,n] = dot(A[m,:], W[n,:]), M=32. 64 n per block; warp g owns 8 n.
// W: cp.async 2-stage smem pipeline (no registers). A: reg-prefetch + swizzled
// smem. Compute: per k4, one lane-indexed av LDS.128 feeds 8 n (16 fma2) —
// halves the per-output smem-crossbar traffic vs the 32n version.
// aload 0: A from memory. 1: A = attn combine (out_w; A ptr unused).
__global__ void __launch_bounds__(256, 2)
gemm64_kernel(const float* __restrict__ A, const float* __restrict__ W,
              const float* __restrict__ res, float* __restrict__ Cout,
              int N, int K, int kslen, int mode, int aload) {
    extern __shared__ float4 smem4[];
    float4* w_s0 = smem4;                 // [2][64 rows][32 f4]
    float4* a_s0 = smem4 + 4096;          // [2][32 cols][32 f4] swizzled

    int t = threadIdx.x;
    int m = t & 31;
    int g = t >> 5;
    int nblocks = N >> 6;
    int nb = blockIdx.x % nblocks;
    int ks = blockIdx.x / nblocks;
    int k0 = ks * kslen;

    int lrow = t >> 5;          // 0..7
    int lcol = t & 31;
    const float* Wg = W + (size_t)(nb * 64 + lrow) * K + k0 + (size_t)lcol * 4;
    const float* Ag = A + (size_t)lrow * K + k0 + (size_t)lcol * 4;
    int nt = kslen >> 7;

    uint32_t w_u32 = smem_u32(w_s0);

    // issue W tile 0
#pragma unroll
    for (int i = 0; i < 8; i++)
        cp_async16(w_u32 + (uint32_t)(((lrow + 8 * i) * 32 + lcol) * 16),
                   Wg + (size_t)(8 * i) * K);
    cp_commit();

    // A tile 0 into registers
    float4 areg[4];
#pragma unroll
    for (int i = 0; i < 4; i++)
        areg[i] = (aload == 0)
                ? *reinterpret_cast<const float4*>(Ag + (size_t)(8 * i) * K)
                : ld_a_combine(lrow + 8 * i, k0 + lcol * 4);

    unsigned long long acc[8][2];
#pragma unroll
    for (int j = 0; j < 8; j++) { acc[j][0] = 0ull; acc[j][1] = 0ull; }

    for (int it = 0; it < nt; it++) {
        float4* a_s = a_s0 + (it & 1) * 1024;
#pragma unroll
        for (int i = 0; i < 4; i++) {
            int row = lrow + 8 * i;
            a_s[lcol * 32 + (row ^ lcol)] = areg[i];
        }

        if (it + 1 < nt) {
            int kc = (it + 1) * BK_;
            uint32_t wd = w_u32 + (uint32_t)((it + 1) & 1) * 32768u;
#pragma unroll
            for (int i = 0; i < 8; i++)
                cp_async16(wd + (uint32_t)(((lrow + 8 * i) * 32 + lcol) * 16),
                           Wg + (size_t)(8 * i) * K + kc);
            cp_commit();
#pragma unroll
            for (int i = 0; i < 4; i++)
                areg[i] = (aload == 0)
                        ? *reinterpret_cast<const float4*>(Ag + (size_t)(8 * i) * K + kc)
                        : ld_a_combine(lrow + 8 * i, k0 + kc + lcol * 4);
            cp_wait<1>();
        } else {
            cp_wait<0>();
        }
        __syncthreads();

        const float4* wrow = w_s0 + (it & 1) * 2048 + g * 8 * 32;
        const float4* ar   = a_s0 + (it & 1) * 1024;
#pragma unroll 4
        for (int k4 = 0; k4 < 32; k4++) {
            ulonglong2 av = *reinterpret_cast<const ulonglong2*>(&ar[k4 * 32 + (m ^ k4)]);
#pragma unroll
            for (int j = 0; j < 8; j++) {
                ulonglong2 wv = *reinterpret_cast<const ulonglong2*>(&wrow[j * 32 + k4]);
                fma2(acc[j][0], av.x, wv.x);
                fma2(acc[j][1], av.y, wv.y);
            }
        }
        __syncthreads();
    }

    int n0 = nb * 64 + g * 8;
    if (kslen == K) {
#pragma unroll
        for (int j = 0; j < 8; j++) {
            float2 lo = *reinterpret_cast<float2*>(&acc[j][0]);
            float2 hi = *reinterpret_cast<float2*>(&acc[j][1]);
            float v = (lo.x + lo.y) + (hi.x + hi.y);
            int n = n0 + j;
            if (mode == 1)      v += res[(size_t)m * N + n];
            else if (mode == 2) v = fmaxf(v, 0.f);
            Cout[(size_t)m * N + n] = v;
        }
    } else {
#pragma unroll
        for (int j = 0; j < 8; j++) {
            float2 lo = *reinterpret_cast<float2*>(&acc[j][0]);
            float2 hi = *reinterpret_cast<float2*>(&acc[j][1]);
            Cout[(size_t)(ks * 32 + m) * N + n0 + j] = (lo.x + lo.y) + (hi.x + hi.y);
        }
    }
}

// split-K reduce: C = mode(sum_ks P, res)
__global__ void reduce_kernel(const float* __restrict__ P, const float* __restrict__ res,
                              float* __restrict__ C, int N, int KS, int mode) {
    int i = blockIdx.x * 256 + threadIdx.x;
    if (i >= 32 * N) return;
    float s = 0.f;
    for (int ks = 0; ks < KS; ks++) s += P[(size_t)ks * 32 * N + i];
    if (mode == 1)      s += res[i];
    else if (mode == 2) s = fmaxf(s, 0.f);
    C[i] = s;
}

// ------------- split attention (r8, proven) ---------------------------------
__global__ void __launch_bounds__(256, 2)
attn_split_kernel(const float* __restrict__ partQ,
                  const float* __restrict__ pk, const float* __restrict__ pv,
                  float* __restrict__ ok, float* __restrict__ ov) {
    extern __shared__ float sm[];
    float* q_sm  = sm;            // [4][64] pre-scaled
    float* kn    = sm + 256;      // new K rows [4][64]
    float* vn    = sm + 512;      // new V rows [4][64]
    float* red   = sm + 768;      // [256]
    float* mls   = sm + 1024;     // [4] local max (pad 32)
    float* opart = sm + 1056;     // [8 warps][4 qq][64 d]
    float* scT   = sm + 3104;     // [2052][4] interleaved scores

    int t = threadIdx.x;
    int bh = blockIdx.x >> 1;
    int j  = blockIdx.x & 1;
    int b = bh >> 4;
    int h = bh & 15;
    int s0 = j * HALF_;
    int nrows = HALF_ + (j ? Q_ : 0);

    {   // fused qkv split-K reduce: sum 4 partial slices (N=3072)
        int qq = t >> 6, d = t & 63;
        int m = b * Q_ + qq;
        int col = h * HD_ + d;
        float qv = 0.f, kv = 0.f, vv = 0.f;
#pragma unroll
        for (int s = 0; s < 4; s++) {
            const float* pr = partQ + (size_t)(s * 32 + m) * (3 * D_) + col;
            qv += pr[0];
            kv += pr[D_];
            vv += pr[2 * D_];
        }
        q_sm[t] = qv * SCALE_;
        kn[t]   = kv;
        vn[t]   = vv;
    }
    __syncthreads();

    int w   = t >> 5;   // 0..7
    int l   = t & 31;
    int sub = l >> 4;
    int dq  = l & 15;

    const float* kb  = pk + (size_t)bh * S_ * HD_;
    float*       okb = ok + (size_t)bh * SP_ * HD_;

    float4 q0 = *reinterpret_cast<const float4*>(q_sm +       dq * 4);
    float4 q1 = *reinterpret_cast<const float4*>(q_sm +  64 + dq * 4);
    float4 q2 = *reinterpret_cast<const float4*>(q_sm + 128 + dq * 4);
    float4 q3 = *reinterpret_cast<const float4*>(q_sm + 192 + dq * 4);

    // ---- pass 1: K half-stream -> scores + pres_k ----
    for (int base = w * 8; base < 1024; base += 64) {
        float4 kv[8];
#pragma unroll
        for (int u = 0; u < 8; u++) {
            int rowl = (base + u) * 2 + sub;
            kv[u] = *reinterpret_cast<const float4*>(kb + (size_t)(s0 + rowl) * HD_ + dq * 4);
        }
#pragma unroll
        for (int u = 0; u < 8; u++) {
            int rowl = (base + u) * 2 + sub;
            *reinterpret_cast<float4*>(okb + (size_t)(s0 + rowl) * HD_ + dq * 4) = kv[u];
            float p0 = kv[u].x * q0.x + kv[u].y * q0.y + kv[u].z * q0.z + kv[u].w * q0.w;
            float p1 = kv[u].x * q1.x + kv[u].y * q1.y + kv[u].z * q1.z + kv[u].w * q1.w;
            float p2 = kv[u].x * q2.x + kv[u].y * q2.y + kv[u].z * q2.z + kv[u].w * q2.w;
            float p3 = kv[u].x * q3.x + kv[u].y * q3.y + kv[u].z * q3.z + kv[u].w * q3.w;
#pragma unroll
            for (int off = 1; off <= 8; off <<= 1) {
                p0 += __shfl_xor_sync(0xffffffffu, p0, off);
                p1 += __shfl_xor_sync(0xffffffffu, p1, off);
                p2 += __shfl_xor_sync(0xffffffffu, p2, off);
                p3 += __shfl_xor_sync(0xffffffffu, p3, off);
            }
            if (dq == 0)
                *reinterpret_cast<float4*>(scT + rowl * 4) = make_float4(p0, p1, p2, p3);
        }
    }
    if (j == 1 && w < 2) {   // new K rows 4096..4099 (local 2048..2051)
        int r2 = w * 2 + sub;
        int rowl = HALF_ + r2;
        float4 kv = *reinterpret_cast<const float4*>(kn + r2 * HD_ + dq * 4);
        *reinterpret_cast<float4*>(okb + (size_t)(S_ + r2) * HD_ + dq * 4) = kv;
        float p0 = kv.x * q0.x + kv.y * q0.y + kv.z * q0.z + kv.w * q0.w;
        float p1 = kv.x * q1.x + kv.y * q1.y + kv.z * q1.z + kv.w * q1.w;
        float p2 = kv.x * q2.x + kv.y * q2.y + kv.z * q2.z + kv.w * q2.w;
        float p3 = kv.x * q3.x + kv.y * q3.y + kv.z * q3.z + kv.w * q3.w;
#pragma unroll
        for (int off = 1; off <= 8; off <<= 1) {
            p0 += __shfl_xor_sync(0xffffffffu, p0, off);
            p1 += __shfl_xor_sync(0xffffffffu, p1, off);
            p2 += __shfl_xor_sync(0xffffffffu, p2, off);
            p3 += __shfl_xor_sync(0xffffffffu, p3, off);
        }
        if (dq == 0)
            *reinterpret_cast<float4*>(scT + rowl * 4) = make_float4(p0, p1, p2, p3);
    }
    __syncthreads();

    // ---- local softmax stats over scT[s][qq]; store exp(sc - m_loc) ----
    {
        int qq = t & 3, sidx = t >> 2;   // 64 s-threads per qq
        float mx = -1e30f;
        for (int s = sidx; s < nrows; s += 64) mx = fmaxf(mx, scT[s * 4 + qq]);
        red[t] = mx;
        __syncthreads();
        for (int wd = 128; wd >= 4; wd >>= 1) {
            if (t < wd) red[t] = fmaxf(red[t], red[t + wd]);
            __syncthreads();
        }
        if (t < 4) mls[t] = red[t];
        __syncthreads();
        float gm = mls[qq];
        float sum = 0.f;
        for (int s = sidx; s < nrows; s += 64) {
            float e = __expf(scT[s * 4 + qq] - gm);
            scT[s * 4 + qq] = e;
            sum += e;
        }
        __syncthreads();
        red[t] = sum;
        __syncthreads();
        for (int wd = 128; wd >= 4; wd >>= 1) {
            if (t < wd) red[t] += red[t + wd];
            __syncthreads();
        }
        if (t < 4) {
            int bj = bh * 2 + j;
            g_ms[bj * 8 + t]     = mls[t];    // local max
            g_ms[bj * 8 + 4 + t] = red[t];    // local sum
        }
        __syncthreads();
    }

    // ---- pass 2: V half-stream -> unnormalized partial O + pres_v ----
    const float* vb  = pv + (size_t)bh * S_ * HD_;
    float*       ovb = ov + (size_t)bh * SP_ * HD_;
    float4 a0 = make_float4(0.f, 0.f, 0.f, 0.f);
    float4 a1 = a0, a2 = a0, a3 = a0;

    for (int base = w * 8; base < 1024; base += 64) {
        float4 vv[8];
#pragma unroll
        for (int u = 0; u < 8; u++) {
            int rowl = (base + u) * 2 + sub;
            vv[u] = *reinterpret_cast<const float4*>(vb + (size_t)(s0 + rowl) * HD_ + dq * 4);
        }
#pragma unroll
        for (int u = 0; u < 8; u++) {
            int rowl = (base + u) * 2 + sub;
            *reinterpret_cast<float4*>(ovb + (size_t)(s0 + rowl) * HD_ + dq * 4) = vv[u];
            float4 p = *reinterpret_cast<const float4*>(scT + rowl * 4);
            a0.x += p.x * vv[u].x; a0.y += p.x * vv[u].y; a0.z += p.x * vv[u].z; a0.w += p.x * vv[u].w;
            a1.x += p.y * vv[u].x; a1.y += p.y * vv[u].y; a1.z += p.y * vv[u].z; a1.w += p.y * vv[u].w;
            a2.x += p.z * vv[u].x; a2.y += p.z * vv[u].y; a2.z += p.z * vv[u].z; a2.w += p.z * vv[u].w;
            a3.x += p.w * vv[u].x; a3.y += p.w * vv[u].y; a3.z += p.w * vv[u].z; a3.w += p.w * vv[u].w;
        }
    }
    if (j == 1 && w < 2) {
        int r2 = w * 2 + sub;
        int rowl = HALF_ + r2;
        float4 vv = *reinterpret_cast<const float4*>(vn + r2 * HD_ + dq * 4);
        *reinterpret_cast<float4*>(ovb + (size_t)(S_ + r2) * HD_ + dq * 4) = vv;
        float4 p = *reinterpret_cast<const float4*>(scT + rowl * 4);
        a0.x += p.x * vv.x; a0.y += p.x * vv.y; a0.z += p.x * vv.z; a0.w += p.x * vv.w;
        a1.x += p.y * vv.x; a1.y += p.y * vv.y; a1.z += p.y * vv.z; a1.w += p.y * vv.w;
        a2.x += p.z * vv.x; a2.y += p.z * vv.y; a2.z += p.z * vv.z; a2.w += p.z * vv.w;
        a3.x += p.w * vv.x; a3.y += p.w * vv.y; a3.z += p.w * vv.z; a3.w += p.w * vv.w;
    }

    a0.x += __shfl_xor_sync(0xffffffffu, a0.x, 16); a0.y += __shfl_xor_sync(0xffffffffu, a0.y, 16);
    a0.z += __shfl_xor_sync(0xffffffffu, a0.z, 16); a0.w += __shfl_xor_sync(0xffffffffu, a0.w, 16);
    a1.x += __shfl_xor_sync(0xffffffffu, a1.x, 16); a1.y += __shfl_xor_sync(0xffffffffu, a1.y, 16);
    a1.z += __shfl_xor_sync(0xffffffffu, a1.z, 16); a1.w += __shfl_xor_sync(0xffffffffu, a1.w, 16);
    a2.x += __shfl_xor_sync(0xffffffffu, a2.x, 16); a2.y += __shfl_xor_sync(0xffffffffu, a2.y, 16);
    a2.z += __shfl_xor_sync(0xffffffffu, a2.z, 16); a2.w += __shfl_xor_sync(0xffffffffu, a2.w, 16);
    a3.x += __shfl_xor_sync(0xffffffffu, a3.x, 16); a3.y += __shfl_xor_sync(0xffffffffu, a3.y, 16);
    a3.z += __shfl_xor_sync(0xffffffffu, a3.z, 16); a3.w += __shfl_xor_sync(0xffffffffu, a3.w, 16);

    if (sub == 0) {
        *reinterpret_cast<float4*>(opart + (w * 4 + 0) * 64 + dq * 4) = a0;
        *reinterpret_cast<float4*>(opart + (w * 4 + 1) * 64 + dq * 4) = a1;
        *reinterpret_cast<float4*>(opart + (w * 4 + 2) * 64 + dq * 4) = a2;
        *reinterpret_cast<float4*>(opart + (w * 4 + 3) * 64 + dq * 4) = a3;
    }
    __syncthreads();

    {   // cross-warp reduce, write UNNORMALIZED partial to scratch
        int qq = t >> 6, d = t & 63;
        float s = 0.f;
#pragma unroll
        for (int ww = 0; ww < 8; ww++)
            s += opart[(ww * 4 + qq) * 64 + d];
        g_opart[((size_t)(bh * 2 + j) * 4 + qq) * 64 + d] = s;
    }
}

// ------------------------------- launcher (r8 config, gemm64) ---------------
extern "C" void kernel_launch(void* const* d_in, const int* in_sizes, int n_in,
                              void* d_out, int out_size) {
    const int*   ids    = (const int*)d_in[0];
    const int*   pos    = (const int*)d_in[1];
    const float* past_k = (const float*)d_in[2];
    const float* past_v = (const float*)d_in[3];
    const float* emb    = (const float*)d_in[4];
    const float* pemb   = (const float*)d_in[5];
    const float* qkv_w  = (const float*)d_in[6];
    const float* out_w  = (const float*)d_in[7];
    const float* fc1_w  = (const float*)d_in[8];
    const float* fc2_w  = (const float*)d_in[9];
    const float* lm_w   = (const float*)d_in[10];

    float* out    = (float*)d_out;
    float* logits = out;
    float* pres_k = out + (size_t)M32 * V_;
    float* pres_v = pres_k + (size_t)L_ * B_ * H_ * SP_ * HD_;

    float *x, *hb, *part;
    cudaGetSymbolAddress((void**)&x,    g_x);
    cudaGetSymbolAddress((void**)&hb,   g_h);
    cudaGetSymbolAddress((void**)&part, g_part);

    const int ATTN_SMEM = (3104 + (HALF_ + Q_) * 4) * 4;   // 45248 B
    cudaFuncSetAttribute(attn_split_kernel, cudaFuncAttributeMaxDynamicSharedMemorySize, ATTN_SMEM);
    cudaFuncSetAttribute(gemm64_kernel, cudaFuncAttributeMaxDynamicSharedMemorySize, GEMM_SMEM_B);

    embed_kernel<<<M32, 256>>>(ids, pos, emb, pemb);

    for (int l = 0; l < L_; l++) {
        // qkv = x @ qkv_w^T       N=3072 K=1024, 48 nb * splitK4 -> 192 blocks
        gemm64_kernel<<<48 * 4, 256, GEMM_SMEM_B>>>(x, qkv_w + (size_t)l * 3 * D_ * D_,
                                                    nullptr, part + PQ_OFF, 3 * D_, D_, D_ / 4, 0, 0);

        // attention (fused qkv reduce; writes partial O + stats)
        attn_split_kernel<<<B_ * H_ * 2, 256, ATTN_SMEM>>>(
            part + PQ_OFF,
            past_k + (size_t)l * B_ * H_ * S_ * HD_,
            past_v + (size_t)l * B_ * H_ * S_ * HD_,
            pres_k + (size_t)l * B_ * H_ * SP_ * HD_,
            pres_v + (size_t)l * B_ * H_ * SP_ * HD_);

        // x += o @ out_w^T        N=1024 K=1024, 16 nb * splitK8 -> 128 blocks; A = combine
        gemm64_kernel<<<16 * 8, 256, GEMM_SMEM_B>>>(nullptr, out_w + (size_t)l * D_ * D_,
                                                    nullptr, part + PO_OFF, D_, D_, D_ / 8, 0, 1);
        reduce_kernel<<<(32 * D_) / 256, 256>>>(part + PO_OFF, x, x, D_, 8, 1);

        // h = relu(x @ fc1_w^T)   N=4096 K=1024, 64 nb * splitK4 -> 256 blocks
        gemm64_kernel<<<64 * 4, 256, GEMM_SMEM_B>>>(x, fc1_w + (size_t)l * 4 * D_ * D_,
                                                    nullptr, part + PF1_OFF, 4 * D_, D_, D_ / 4, 0, 0);
        reduce_kernel<<<(32 * 4 * D_) / 256, 256>>>(part + PF1_OFF, nullptr, hb, 4 * D_, 4, 2);

        // x += h @ fc2_w^T        N=1024 K=4096, 16 nb * splitK8 -> 128 blocks
        gemm64_kernel<<<16 * 8, 256, GEMM_SMEM_B>>>(hb, fc2_w + (size_t)l * D_ * 4 * D_,
                                                    nullptr, part + PF2_OFF, D_, 4 * D_, 4 * D_ / 8, 0, 0);
        reduce_kernel<<<(32 * D_) / 256, 256>>>(part + PF2_OFF, x, x, D_, 8, 1);
    }

    // logits = x @ lm_head^T      N=32000 K=1024, 500 blocks, nt=8
    gemm64_kernel<<<500, 256, GEMM_SMEM_B>>>(x, lm_w, nullptr, logits, V_, D_, D_, 0, 0);
}

// round 13
// speedup vs baseline: 1.1142x; 1.0379x over previous
#include <cuda_runtime.h>
#include <math.h>
#include <stdint.h>

#define L_  4
#define B_  8
#define H_  16
#define S_  4096
#define HD_ 64
#define D_  1024
#define Q_  4
#define V_  32000
#define SP_ (S_ + Q_)      // 4100
#define M32 (B_ * Q_)      // 32
#define SCALE_ 0.125f      // 1/sqrt(64)
#define BK_ 128            // k per tile
#define HALF_ 2048         // rows per attention split block

// partial-buffer offsets (floats) inside g_part
#define PQ_OFF  0                         // qkv partials  4*32*3072
#define PF1_OFF 655360                    // fc1 partials  4*32*4096

#define GEMM_SMEM_B 98304                 // 2*32KB W + 2*16KB A

// ------------------------- scratch (no allocs allowed) ----------------------
__device__ float g_x[M32 * D_];
__device__ float g_h[M32 * 4 * D_];
__device__ float g_part[2097152];             // split-K partials (8 MB)
__device__ float g_opart[2 * 128 * 4 * 64];   // attn partial O [bh*2+j][qq][d]
__device__ float g_ms[128 * 2 * 8];           // attn [bh*2+j][m0..3, s0..3]

// ------------------------------ helpers -------------------------------------
__device__ __forceinline__ void fma2(unsigned long long& d,
                                     unsigned long long a, unsigned long long b) {
    asm("fma.rn.f32x2 %0, %1, %2, %0;" : "+l"(d) : "l"(a), "l"(b));
}
__device__ __forceinline__ void cp_async16(uint32_t dst, const void* src) {
    asm volatile("cp.async.cg.shared.global [%0], [%1], 16;" :: "r"(dst), "l"(src));
}
__device__ __forceinline__ void cp_commit() {
    asm volatile("cp.async.commit_group;");
}
template <int N>
__device__ __forceinline__ void cp_wait() {
    asm volatile("cp.async.wait_group %0;" :: "n"(N));
}
__device__ __forceinline__ uint32_t smem_u32(const void* p) {
    uint64_t tmp;
    asm("cvta.to.shared.u64 %0, %1;" : "=l"(tmp) : "l"(p));
    return (uint32_t)tmp;
}

// aload=1: inline attn-combine A staging (out_w GEMM)
__device__ __forceinline__ float4 ld_a_combine(int mrow, int col) {
    int b = mrow >> 2, qq = mrow & 3;
    int h = col >> 6, d = col & 63;
    int bh = b * 16 + h;
    float m0 = g_ms[(bh * 2 + 0) * 8 + qq], s0 = g_ms[(bh * 2 + 0) * 8 + 4 + qq];
    float m1 = g_ms[(bh * 2 + 1) * 8 + qq], s1 = g_ms[(bh * 2 + 1) * 8 + 4 + qq];
    float M = fmaxf(m0, m1);
    float w0 = __expf(m0 - M), w1 = __expf(m1 - M);
    float inv = 1.f / (s0 * w0 + s1 * w1);
    w0 *= inv; w1 *= inv;
    float4 o0 = *reinterpret_cast<const float4*>(&g_opart[((size_t)(bh * 2 + 0) * 4 + qq) * 64 + d]);
    float4 o1 = *reinterpret_cast<const float4*>(&g_opart[((size_t)(bh * 2 + 1) * 4 + qq) * 64 + d]);
    return make_float4(o0.x * w0 + o1.x * w1, o0.y * w0 + o1.y * w1,
                       o0.z * w0 + o1.z * w1, o0.w * w0 + o1.w * w1);
}

// ------------------------------ embedding -----------------------------------
__global__ void embed_kernel(const int* __restrict__ ids, const int* __restrict__ pos,
                             const float* __restrict__ emb, const float* __restrict__ pemb) {
    int m = blockIdx.x;
    int id = ids[m];
    int p  = pos[m];
    const float* e  = emb  + (size_t)id * D_;
    const float* pe = pemb + (size_t)p  * D_;
    for (int d = threadIdx.x; d < D_; d += blockDim.x)
        g_x[m * D_ + d] = e[d] + pe[d];
}

// ------------------------------ skinny GEMM, N-tile 64 ----------------------
// modes: kslen==K -> 0 store / 1 +res / 2 relu.
//        kslen<K  -> mode 3: atomicAdd partial into Cout (residual accumulate),
//                    else: store partial slice to Cout (g_part layout).
// aload 0: A from memory. 1: A = attn combine (out_w; A ptr unused).
__global__ void __launch_bounds__(256, 2)
gemm64_kernel(const float* __restrict__ A, const float* __restrict__ W,
              const float* __restrict__ res, float* __restrict__ Cout,
              int N, int K, int kslen, int mode, int aload) {
    extern __shared__ float4 smem4[];
    float4* w_s0 = smem4;                 // [2][64 rows][32 f4]
    float4* a_s0 = smem4 + 4096;          // [2][32 cols][32 f4] swizzled

    int t = threadIdx.x;
    int m = t & 31;
    int g = t >> 5;
    int nblocks = N >> 6;
    int nb = blockIdx.x % nblocks;
    int ks = blockIdx.x / nblocks;
    int k0 = ks * kslen;

    int lrow = t >> 5;          // 0..7
    int lcol = t & 31;
    const float* Wg = W + (size_t)(nb * 64 + lrow) * K + k0 + (size_t)lcol * 4;
    const float* Ag = A + (size_t)lrow * K + k0 + (size_t)lcol * 4;
    int nt = kslen >> 7;

    uint32_t w_u32 = smem_u32(w_s0);

    // issue W tile 0
#pragma unroll
    for (int i = 0; i < 8; i++)
        cp_async16(w_u32 + (uint32_t)(((lrow + 8 * i) * 32 + lcol) * 16),
                   Wg + (size_t)(8 * i) * K);
    cp_commit();

    // A tile 0 into registers
    float4 areg[4];
#pragma unroll
    for (int i = 0; i < 4; i++)
        areg[i] = (aload == 0)
                ? *reinterpret_cast<const float4*>(Ag + (size_t)(8 * i) * K)
                : ld_a_combine(lrow + 8 * i, k0 + lcol * 4);

    unsigned long long acc[8][2];
#pragma unroll
    for (int j = 0; j < 8; j++) { acc[j][0] = 0ull; acc[j][1] = 0ull; }

    for (int it = 0; it < nt; it++) {
        float4* a_s = a_s0 + (it & 1) * 1024;
#pragma unroll
        for (int i = 0; i < 4; i++) {
            int row = lrow + 8 * i;
            a_s[lcol * 32 + (row ^ lcol)] = areg[i];
        }

        if (it + 1 < nt) {
            int kc = (it + 1) * BK_;
            uint32_t wd = w_u32 + (uint32_t)((it + 1) & 1) * 32768u;
#pragma unroll
            for (int i = 0; i < 8; i++)
                cp_async16(wd + (uint32_t)(((lrow + 8 * i) * 32 + lcol) * 16),
                           Wg + (size_t)(8 * i) * K + kc);
            cp_commit();
#pragma unroll
            for (int i = 0; i < 4; i++)
                areg[i] = (aload == 0)
                        ? *reinterpret_cast<const float4*>(Ag + (size_t)(8 * i) * K + kc)
                        : ld_a_combine(lrow + 8 * i, k0 + kc + lcol * 4);
            cp_wait<1>();
        } else {
            cp_wait<0>();
        }
        __syncthreads();

        const float4* wrow = w_s0 + (it & 1) * 2048 + g * 8 * 32;
        const float4* ar   = a_s0 + (it & 1) * 1024;
#pragma unroll 4
        for (int k4 = 0; k4 < 32; k4++) {
            ulonglong2 av = *reinterpret_cast<const ulonglong2*>(&ar[k4 * 32 + (m ^ k4)]);
#pragma unroll
            for (int j = 0; j < 8; j++) {
                ulonglong2 wv = *reinterpret_cast<const ulonglong2*>(&wrow[j * 32 + k4]);
                fma2(acc[j][0], av.x, wv.x);
                fma2(acc[j][1], av.y, wv.y);
            }
        }
        __syncthreads();
    }

    int n0 = nb * 64 + g * 8;
    if (kslen == K) {
#pragma unroll
        for (int j = 0; j < 8; j++) {
            float2 lo = *reinterpret_cast<float2*>(&acc[j][0]);
            float2 hi = *reinterpret_cast<float2*>(&acc[j][1]);
            float v = (lo.x + lo.y) + (hi.x + hi.y);
            int n = n0 + j;
            if (mode == 1)      v += res[(size_t)m * N + n];
            else if (mode == 2) v = fmaxf(v, 0.f);
            Cout[(size_t)m * N + n] = v;
        }
    } else if (mode == 3) {
#pragma unroll
        for (int j = 0; j < 8; j++) {
            float2 lo = *reinterpret_cast<float2*>(&acc[j][0]);
            float2 hi = *reinterpret_cast<float2*>(&acc[j][1]);
            atomicAdd(&Cout[(size_t)m * N + n0 + j], (lo.x + lo.y) + (hi.x + hi.y));
        }
    } else {
#pragma unroll
        for (int j = 0; j < 8; j++) {
            float2 lo = *reinterpret_cast<float2*>(&acc[j][0]);
            float2 hi = *reinterpret_cast<float2*>(&acc[j][1]);
            Cout[(size_t)(ks * 32 + m) * N + n0 + j] = (lo.x + lo.y) + (hi.x + hi.y);
        }
    }
}

// split-K reduce: C = mode(sum_ks P, res)
__global__ void reduce_kernel(const float* __restrict__ P, const float* __restrict__ res,
                              float* __restrict__ C, int N, int KS, int mode) {
    int i = blockIdx.x * 256 + threadIdx.x;
    if (i >= 32 * N) return;
    float s = 0.f;
    for (int ks = 0; ks < KS; ks++) s += P[(size_t)ks * 32 * N + i];
    if (mode == 1)      s += res[i];
    else if (mode == 2) s = fmaxf(s, 0.f);
    C[i] = s;
}

// ------------- split attention (r8, proven) ---------------------------------
__global__ void __launch_bounds__(256, 2)
attn_split_kernel(const float* __restrict__ partQ,
                  const float* __restrict__ pk, const float* __restrict__ pv,
                  float* __restrict__ ok, float* __restrict__ ov) {
    extern __shared__ float sm[];
    float* q_sm  = sm;            // [4][64] pre-scaled
    float* kn    = sm + 256;      // new K rows [4][64]
    float* vn    = sm + 512;      // new V rows [4][64]
    float* red   = sm + 768;      // [256]
    float* mls   = sm + 1024;     // [4] local max (pad 32)
    float* opart = sm + 1056;     // [8 warps][4 qq][64 d]
    float* scT   = sm + 3104;     // [2052][4] interleaved scores

    int t = threadIdx.x;
    int bh = blockIdx.x >> 1;
    int j  = blockIdx.x & 1;
    int b = bh >> 4;
    int h = bh & 15;
    int s0 = j * HALF_;
    int nrows = HALF_ + (j ? Q_ : 0);

    {   // fused qkv split-K reduce: sum 4 partial slices (N=3072)
        int qq = t >> 6, d = t & 63;
        int m = b * Q_ + qq;
        int col = h * HD_ + d;
        float qv = 0.f, kv = 0.f, vv = 0.f;
#pragma unroll
        for (int s = 0; s < 4; s++) {
            const float* pr = partQ + (size_t)(s * 32 + m) * (3 * D_) + col;
            qv += pr[0];
            kv += pr[D_];
            vv += pr[2 * D_];
        }
        q_sm[t] = qv * SCALE_;
        kn[t]   = kv;
        vn[t]   = vv;
    }
    __syncthreads();

    int w   = t >> 5;   // 0..7
    int l   = t & 31;
    int sub = l >> 4;
    int dq  = l & 15;

    const float* kb  = pk + (size_t)bh * S_ * HD_;
    float*       okb = ok + (size_t)bh * SP_ * HD_;

    float4 q0 = *reinterpret_cast<const float4*>(q_sm +       dq * 4);
    float4 q1 = *reinterpret_cast<const float4*>(q_sm +  64 + dq * 4);
    float4 q2 = *reinterpret_cast<const float4*>(q_sm + 128 + dq * 4);
    float4 q3 = *reinterpret_cast<const float4*>(q_sm + 192 + dq * 4);

    // ---- pass 1: K half-stream -> scores + pres_k ----
    for (int base = w * 8; base < 1024; base += 64) {
        float4 kv[8];
#pragma unroll
        for (int u = 0; u < 8; u++) {
            int rowl = (base + u) * 2 + sub;
            kv[u] = *reinterpret_cast<const float4*>(kb + (size_t)(s0 + rowl) * HD_ + dq * 4);
        }
#pragma unroll
        for (int u = 0; u < 8; u++) {
            int rowl = (base + u) * 2 + sub;
            *reinterpret_cast<float4*>(okb + (size_t)(s0 + rowl) * HD_ + dq * 4) = kv[u];
            float p0 = kv[u].x * q0.x + kv[u].y * q0.y + kv[u].z * q0.z + kv[u].w * q0.w;
            float p1 = kv[u].x * q1.x + kv[u].y * q1.y + kv[u].z * q1.z + kv[u].w * q1.w;
            float p2 = kv[u].x * q2.x + kv[u].y * q2.y + kv[u].z * q2.z + kv[u].w * q2.w;
            float p3 = kv[u].x * q3.x + kv[u].y * q3.y + kv[u].z * q3.z + kv[u].w * q3.w;
#pragma unroll
            for (int off = 1; off <= 8; off <<= 1) {
                p0 += __shfl_xor_sync(0xffffffffu, p0, off);
                p1 += __shfl_xor_sync(0xffffffffu, p1, off);
                p2 += __shfl_xor_sync(0xffffffffu, p2, off);
                p3 += __shfl_xor_sync(0xffffffffu, p3, off);
            }
            if (dq == 0)
                *reinterpret_cast<float4*>(scT + rowl * 4) = make_float4(p0, p1, p2, p3);
        }
    }
    if (j == 1 && w < 2) {   // new K rows 4096..4099 (local 2048..2051)
        int r2 = w * 2 + sub;
        int rowl = HALF_ + r2;
        float4 kv = *reinterpret_cast<const float4*>(kn + r2 * HD_ + dq * 4);
        *reinterpret_cast<float4*>(okb + (size_t)(S_ + r2) * HD_ + dq * 4) = kv;
        float p0 = kv.x * q0.x + kv.y * q0.y + kv.z * q0.z + kv.w * q0.w;
        float p1 = kv.x * q1.x + kv.y * q1.y + kv.z * q1.z + kv.w * q1.w;
        float p2 = kv.x * q2.x + kv.y * q2.y + kv.z * q2.z + kv.w * q2.w;
        float p3 = kv.x * q3.x + kv.y * q3.y + kv.z * q3.z + kv.w * q3.w;
#pragma unroll
        for (int off = 1; off <= 8; off <<= 1) {
            p0 += __shfl_xor_sync(0xffffffffu, p0, off);
            p1 += __shfl_xor_sync(0xffffffffu, p1, off);
            p2 += __shfl_xor_sync(0xffffffffu, p2, off);
            p3 += __shfl_xor_sync(0xffffffffu, p3, off);
        }
        if (dq == 0)
            *reinterpret_cast<float4*>(scT + rowl * 4) = make_float4(p0, p1, p2, p3);
    }
    __syncthreads();

    // ---- local softmax stats over scT[s][qq]; store exp(sc - m_loc) ----
    {
        int qq = t & 3, sidx = t >> 2;   // 64 s-threads per qq
        float mx = -1e30f;
        for (int s = sidx; s < nrows; s += 64) mx = fmaxf(mx, scT[s * 4 + qq]);
        red[t] = mx;
        __syncthreads();
        for (int wd = 128; wd >= 4; wd >>= 1) {
            if (t < wd) red[t] = fmaxf(red[t], red[t + wd]);
            __syncthreads();
        }
        if (t < 4) mls[t] = red[t];
        __syncthreads();
        float gm = mls[qq];
        float sum = 0.f;
        for (int s = sidx; s < nrows; s += 64) {
            float e = __expf(scT[s * 4 + qq] - gm);
            scT[s * 4 + qq] = e;
            sum += e;
        }
        __syncthreads();
        red[t] = sum;
        __syncthreads();
        for (int wd = 128; wd >= 4; wd >>= 1) {
            if (t < wd) red[t] += red[t + wd];
            __syncthreads();
        }
        if (t < 4) {
            int bj = bh * 2 + j;
            g_ms[bj * 8 + t]     = mls[t];    // local max
            g_ms[bj * 8 + 4 + t] = red[t];    // local sum
        }
        __syncthreads();
    }

    // ---- pass 2: V half-stream -> unnormalized partial O + pres_v ----
    const float* vb  = pv + (size_t)bh * S_ * HD_;
    float*       ovb = ov + (size_t)bh * SP_ * HD_;
    float4 a0 = make_float4(0.f, 0.f, 0.f, 0.f);
    float4 a1 = a0, a2 = a0, a3 = a0;

    for (int base = w * 8; base < 1024; base += 64) {
        float4 vv[8];
#pragma unroll
        for (int u = 0; u < 8; u++) {
            int rowl = (base + u) * 2 + sub;
            vv[u] = *reinterpret_cast<const float4*>(vb + (size_t)(s0 + rowl) * HD_ + dq * 4);
        }
#pragma unroll
        for (int u = 0; u < 8; u++) {
            int rowl = (base + u) * 2 + sub;
            *reinterpret_cast<float4*>(ovb + (size_t)(s0 + rowl) * HD_ + dq * 4) = vv[u];
            float4 p = *reinterpret_cast<const float4*>(scT + rowl * 4);
            a0.x += p.x * vv[u].x; a0.y += p.x * vv[u].y; a0.z += p.x * vv[u].z; a0.w += p.x * vv[u].w;
            a1.x += p.y * vv[u].x; a1.y += p.y * vv[u].y; a1.z += p.y * vv[u].z; a1.w += p.y * vv[u].w;
            a2.x += p.z * vv[u].x; a2.y += p.z * vv[u].y; a2.z += p.z * vv[u].z; a2.w += p.z * vv[u].w;
            a3.x += p.w * vv[u].x; a3.y += p.w * vv[u].y; a3.z += p.w * vv[u].z; a3.w += p.w * vv[u].w;
        }
    }
    if (j == 1 && w < 2) {
        int r2 = w * 2 + sub;
        int rowl = HALF_ + r2;
        float4 vv = *reinterpret_cast<const float4*>(vn + r2 * HD_ + dq * 4);
        *reinterpret_cast<float4*>(ovb + (size_t)(S_ + r2) * HD_ + dq * 4) = vv;
        float4 p = *reinterpret_cast<const float4*>(scT + rowl * 4);
        a0.x += p.x * vv.x; a0.y += p.x * vv.y; a0.z += p.x * vv.z; a0.w += p.x * vv.w;
        a1.x += p.y * vv.x; a1.y += p.y * vv.y; a1.z += p.y * vv.z; a1.w += p.y * vv.w;
        a2.x += p.z * vv.x; a2.y += p.z * vv.y; a2.z += p.z * vv.z; a2.w += p.z * vv.w;
        a3.x += p.w * vv.x; a3.y += p.w * vv.y; a3.z += p.w * vv.z; a3.w += p.w * vv.w;
    }

    a0.x += __shfl_xor_sync(0xffffffffu, a0.x, 16); a0.y += __shfl_xor_sync(0xffffffffu, a0.y, 16);
    a0.z += __shfl_xor_sync(0xffffffffu, a0.z, 16); a0.w += __shfl_xor_sync(0xffffffffu, a0.w, 16);
    a1.x += __shfl_xor_sync(0xffffffffu, a1.x, 16); a1.y += __shfl_xor_sync(0xffffffffu, a1.y, 16);
    a1.z += __shfl_xor_sync(0xffffffffu, a1.z, 16); a1.w += __shfl_xor_sync(0xffffffffu, a1.w, 16);
    a2.x += __shfl_xor_sync(0xffffffffu, a2.x, 16); a2.y += __shfl_xor_sync(0xffffffffu, a2.y, 16);
    a2.z += __shfl_xor_sync(0xffffffffu, a2.z, 16); a2.w += __shfl_xor_sync(0xffffffffu, a2.w, 16);
    a3.x += __shfl_xor_sync(0xffffffffu, a3.x, 16); a3.y += __shfl_xor_sync(0xffffffffu, a3.y, 16);
    a3.z += __shfl_xor_sync(0xffffffffu, a3.z, 16); a3.w += __shfl_xor_sync(0xffffffffu, a3.w, 16);

    if (sub == 0) {
        *reinterpret_cast<float4*>(opart + (w * 4 + 0) * 64 + dq * 4) = a0;
        *reinterpret_cast<float4*>(opart + (w * 4 + 1) * 64 + dq * 4) = a1;
        *reinterpret_cast<float4*>(opart + (w * 4 + 2) * 64 + dq * 4) = a2;
        *reinterpret_cast<float4*>(opart + (w * 4 + 3) * 64 + dq * 4) = a3;
    }
    __syncthreads();

    {   // cross-warp reduce, write UNNORMALIZED partial to scratch
        int qq = t >> 6, d = t & 63;
        float s = 0.f;
#pragma unroll
        for (int ww = 0; ww < 8; ww++)
            s += opart[(ww * 4 + qq) * 64 + d];
        g_opart[((size_t)(bh * 2 + j) * 4 + qq) * 64 + d] = s;
    }
}

// ------------------------------- launcher -----------------------------------
extern "C" void kernel_launch(void* const* d_in, const int* in_sizes, int n_in,
                              void* d_out, int out_size) {
    const int*   ids    = (const int*)d_in[0];
    const int*   pos    = (const int*)d_in[1];
    const float* past_k = (const float*)d_in[2];
    const float* past_v = (const float*)d_in[3];
    const float* emb    = (const float*)d_in[4];
    const float* pemb   = (const float*)d_in[5];
    const float* qkv_w  = (const float*)d_in[6];
    const float* out_w  = (const float*)d_in[7];
    const float* fc1_w  = (const float*)d_in[8];
    const float* fc2_w  = (const float*)d_in[9];
    const float* lm_w   = (const float*)d_in[10];

    float* out    = (float*)d_out;
    float* logits = out;
    float* pres_k = out + (size_t)M32 * V_;
    float* pres_v = pres_k + (size_t)L_ * B_ * H_ * SP_ * HD_;

    float *x, *hb, *part;
    cudaGetSymbolAddress((void**)&x,    g_x);
    cudaGetSymbolAddress((void**)&hb,   g_h);
    cudaGetSymbolAddress((void**)&part, g_part);

    const int ATTN_SMEM = (3104 + (HALF_ + Q_) * 4) * 4;   // 45248 B
    cudaFuncSetAttribute(attn_split_kernel, cudaFuncAttributeMaxDynamicSharedMemorySize, ATTN_SMEM);
    cudaFuncSetAttribute(gemm64_kernel, cudaFuncAttributeMaxDynamicSharedMemorySize, GEMM_SMEM_B);

    embed_kernel<<<M32, 256>>>(ids, pos, emb, pemb);

    for (int l = 0; l < L_; l++) {
        // qkv = x @ qkv_w^T       N=3072 K=1024, 48 nb * splitK4 -> 192 blocks
        gemm64_kernel<<<48 * 4, 256, GEMM_SMEM_B>>>(x, qkv_w + (size_t)l * 3 * D_ * D_,
                                                    nullptr, part + PQ_OFF, 3 * D_, D_, D_ / 4, 0, 0);

        // attention (fused qkv reduce; writes partial O + stats)
        attn_split_kernel<<<B_ * H_ * 2, 256, ATTN_SMEM>>>(
            part + PQ_OFF,
            past_k + (size_t)l * B_ * H_ * S_ * HD_,
            past_v + (size_t)l * B_ * H_ * S_ * HD_,
            pres_k + (size_t)l * B_ * H_ * SP_ * HD_,
            pres_v + (size_t)l * B_ * H_ * SP_ * HD_);

        // x += o @ out_w^T        N=1024 K=1024, 16 nb * splitK8 -> 128 blocks
        // A = inline combine; partials atomically accumulated into x (no reduce)
        gemm64_kernel<<<16 * 8, 256, GEMM_SMEM_B>>>(nullptr, out_w + (size_t)l * D_ * D_,
                                                    nullptr, x, D_, D_, D_ / 8, 3, 1);

        // h = relu(x @ fc1_w^T)   N=4096 K=1024, 64 nb * splitK4 -> 256 blocks
        gemm64_kernel<<<64 * 4, 256, GEMM_SMEM_B>>>(x, fc1_w + (size_t)l * 4 * D_ * D_,
                                                    nullptr, part + PF1_OFF, 4 * D_, D_, D_ / 4, 0, 0);
        reduce_kernel<<<(32 * 4 * D_) / 256, 256>>>(part + PF1_OFF, nullptr, hb, 4 * D_, 4, 2);

        // x += h @ fc2_w^T        N=1024 K=4096, 16 nb * splitK8 -> 128 blocks
        // partials atomically accumulated into x (no reduce)
        gemm64_kernel<<<16 * 8, 256, GEMM_SMEM_B>>>(hb, fc2_w + (size_t)l * D_ * 4 * D_,
                                                    nullptr, x, D_, 4 * D_, 4 * D_ / 8, 3, 0);
    }

    // logits = x @ lm_head^T      N=32000 K=1024, 500 blocks, nt=8
    gemm64_kernel<<<500, 256, GEMM_SMEM_B>>>(x, lm_w, nullptr, logits, V_, D_, D_, 0, 0);
}